// round 9
// baseline (speedup 1.0000x reference)
#include <cuda_runtime.h>
#include <cuda_fp16.h>
#include <cstdint>

#define N_NODES 8192
#define IN_F 256
#define OUT_F 64
#define ALPHA 0.3f
#define LOG2E 1.4426950408889634f
#define MAXNZ 1024
#define NWHBLK 512        // 16 rows per block
#define ROWS_PB 4         // attn rows per block

// ---------------- device scratch (no allocations allowed) ----------------
__device__ __half g_Whh[N_NODES * OUT_F];   // Wh fp16 [8192][64], 1 MB (L2-resident)
__device__ float g_src[N_NODES];
__device__ float g_dst[N_NODES];
__device__ float g_blockmax[NWHBLK];

__device__ __forceinline__ float ex2f(float x) {
    float r;
    asm("ex2.approx.f32 %0, %1;" : "=f"(r) : "f"(x));
    return r;
}
__device__ __forceinline__ uint32_t smem_u32(const void* p) {
    uint32_t a;
    asm("{ .reg .u64 t; cvta.to.shared.u64 t, %1; cvt.u32.u64 %0, t; }" : "=r"(a) : "l"(p));
    return a;
}
__device__ __forceinline__ void cp16(uint32_t s, const void* g) {
    asm volatile("cp.async.cg.shared.global [%0], [%1], 16;" :: "r"(s), "l"(g));
}
#define CP_COMMIT() asm volatile("cp.async.commit_group;" ::: "memory")
#define CP_WAIT0()  asm volatile("cp.async.wait_group 0;" ::: "memory")

// ---------------------------------------------------------------------------
// Kernel 1: Wh = h @ W (fp16 out), src/dst projections, per-block dst max.
// Grid 512 (16 rows/block), 128 threads, thread = 2 rows x 4 feats.
// Same micro-tile numerics as R8; doubled schedulable units for residency.
// ---------------------------------------------------------------------------
__global__ __launch_bounds__(128) void wh_kernel(const float* __restrict__ h,
                                                 const float* __restrict__ W,
                                                 const float* __restrict__ a) {
    __shared__ float sh[16][68];    // h tile, padded
    __shared__ float sW[64][64];    // W tile (k-major)
    __shared__ float dtile[16];
    const int tid = threadIdx.x;
    const int tx = tid & 15;        // feat group (4 feats)
    const int ty = tid >> 4;        // row pair (rows 2ty, 2ty+1), 0..7
    const int I0 = blockIdx.x * 16;

    float acc0[4] = {}, acc1[4] = {};

    for (int kt = 0; kt < 4; kt++) {
        __syncthreads();
#pragma unroll
        for (int it = 0; it < 2; it++) {       // h tile: 256 float4 slots
            const int s = tid + it * 128;
            const int r = s >> 4, c = (s & 15) << 2;
            *reinterpret_cast<float4*>(&sh[r][c]) = *reinterpret_cast<const float4*>(
                &h[(size_t)(I0 + r) * IN_F + kt * 64 + c]);
        }
#pragma unroll
        for (int it = 0; it < 8; it++) {       // W tile: 1024 float4 slots
            const int s = tid + it * 128;
            const int r = s >> 4, c = (s & 15) << 2;
            *reinterpret_cast<float4*>(&sW[r][c]) = *reinterpret_cast<const float4*>(
                &W[(size_t)(kt * 64 + r) * OUT_F + c]);
        }
        __syncthreads();
#pragma unroll 4
        for (int k = 0; k < 64; k++) {
            const float4 wv = *reinterpret_cast<const float4*>(&sW[k][tx << 2]);
            const float h0 = sh[ty * 2][k], h1 = sh[ty * 2 + 1][k];
            acc0[0] += h0 * wv.x; acc0[1] += h0 * wv.y; acc0[2] += h0 * wv.z; acc0[3] += h0 * wv.w;
            acc1[0] += h1 * wv.x; acc1[1] += h1 * wv.y; acc1[2] += h1 * wv.z; acc1[3] += h1 * wv.w;
        }
    }

    // fp16 Wh stores
    {
        const __half2 r0a = __floats2half2_rn(acc0[0], acc0[1]);
        const __half2 r0b = __floats2half2_rn(acc0[2], acc0[3]);
        const __half2 r1a = __floats2half2_rn(acc1[0], acc1[1]);
        const __half2 r1b = __floats2half2_rn(acc1[2], acc1[3]);
        uint2 s0, s1;
        s0.x = *reinterpret_cast<const uint32_t*>(&r0a);
        s0.y = *reinterpret_cast<const uint32_t*>(&r0b);
        s1.x = *reinterpret_cast<const uint32_t*>(&r1a);
        s1.y = *reinterpret_cast<const uint32_t*>(&r1b);
        *reinterpret_cast<uint2*>(&g_Whh[(size_t)(I0 + ty * 2) * OUT_F + tx * 4]) = s0;
        *reinterpret_cast<uint2*>(&g_Whh[(size_t)(I0 + ty * 2 + 1) * OUT_F + tx * 4]) = s1;
    }

    const float4 as = *reinterpret_cast<const float4*>(&a[tx << 2]);
    const float4 ad = *reinterpret_cast<const float4*>(&a[OUT_F + (tx << 2)]);
    float sp0 = acc0[0] * as.x + acc0[1] * as.y + acc0[2] * as.z + acc0[3] * as.w;
    float dp0 = acc0[0] * ad.x + acc0[1] * ad.y + acc0[2] * ad.z + acc0[3] * ad.w;
    float sp1 = acc1[0] * as.x + acc1[1] * as.y + acc1[2] * as.z + acc1[3] * as.w;
    float dp1 = acc1[0] * ad.x + acc1[1] * ad.y + acc1[2] * ad.z + acc1[3] * ad.w;
#pragma unroll
    for (int o = 1; o < 16; o <<= 1) {   // reduce across the 16-lane tx group
        sp0 += __shfl_xor_sync(0xffffffffu, sp0, o);
        dp0 += __shfl_xor_sync(0xffffffffu, dp0, o);
        sp1 += __shfl_xor_sync(0xffffffffu, sp1, o);
        dp1 += __shfl_xor_sync(0xffffffffu, dp1, o);
    }
    if (tx == 0) {
        g_src[I0 + ty * 2] = sp0;     g_src[I0 + ty * 2 + 1] = sp1;
        g_dst[I0 + ty * 2] = dp0;     g_dst[I0 + ty * 2 + 1] = dp1;
        dtile[ty * 2] = dp0;          dtile[ty * 2 + 1] = dp1;
    }
    __syncthreads();
    if (tid == 0) {
        float mm = dtile[0];
        for (int q = 1; q < 16; q++) mm = fmaxf(mm, dtile[q]);
        g_blockmax[blockIdx.x] = mm;
    }
}

// ---------------------------------------------------------------------------
// Kernel 2: fused masked attention + aggregation + ELU.
// Block handles 4 consecutive rows; single 32 KB cp.async adj buffer.
// Per row: wait DMA -> regs -> barrier -> fire cp.async for NEXT row
// (streams during compaction+gather) -> R8's ballot/compact/gather path.
// ---------------------------------------------------------------------------
__global__ __launch_bounds__(256) void attn_kernel(const float* __restrict__ adj,
                                                   float* __restrict__ out) {
    __shared__ float sadj[N_NODES / 4 * 4];   // 8192 floats = 32 KB
    __shared__ unsigned mask[256];
    __shared__ int wsum[8], wbase[8];
    __shared__ float fred[8];
    __shared__ int cnt_s;
    __shared__ float dmax_s, den_s;
    __shared__ unsigned short jlist[MAXNZ];
    __shared__ float acc_red[32][OUT_F];
    __shared__ float fin[4][OUT_F];

    const int tid = threadIdx.x;
    const int w = tid >> 5;
    const int lane = tid & 31;
    const int i0 = blockIdx.x * ROWS_PB;

    const uint32_t sadj_b = smem_u32(sadj) + (uint32_t)tid * 16;  // slots k*256+tid

    // ---- prime row 0 ----
#pragma unroll
    for (int k = 0; k < 8; k++)
        cp16(sadj_b + (uint32_t)k * 4096,
             &adj[(size_t)i0 * N_NODES + (k * 256 + tid) * 4]);
    CP_COMMIT();

    // ---- dmax over g_blockmax[512] (overlaps DMA) ----
    {
        float m = fmaxf(g_blockmax[tid], g_blockmax[tid + 256]);
#pragma unroll
        for (int o = 16; o; o >>= 1) m = fmaxf(m, __shfl_xor_sync(0xffffffffu, m, o));
        if (lane == 0) fred[w] = m;
    }
    __syncthreads();
    if (tid == 0) {
        float mm = fred[0];
        for (int q = 1; q < 8; q++) mm = fmaxf(mm, fred[q]);
        dmax_s = mm;
    }
    __syncthreads();
    const float dmax = dmax_s;

    for (int r = 0; r < ROWS_PB; r++) {
        const int i = i0 + r;

        CP_WAIT0();
        __syncthreads();          // row r resident for all threads

        // ---- read adj to registers (8 x float4 per thread) ----
        float4 v[8];
#pragma unroll
        for (int k = 0; k < 8; k++)
            v[k] = *reinterpret_cast<const float4*>(&sadj[(k * 256 + tid) * 4]);
        __syncthreads();          // buffer fully consumed

        // ---- fire DMA for next row: streams during compact+gather ----
        if (r + 1 < ROWS_PB) {
#pragma unroll
            for (int k = 0; k < 8; k++)
                cp16(sadj_b + (uint32_t)k * 4096,
                     &adj[(size_t)(i + 1) * N_NODES + (k * 256 + tid) * 4]);
        }
        CP_COMMIT();

        // ---- ballots -> bitmask ----
#pragma unroll
        for (int k = 0; k < 8; k++) {
            const unsigned b0 = __ballot_sync(0xffffffffu, v[k].x != 0.f);
            const unsigned b1 = __ballot_sync(0xffffffffu, v[k].y != 0.f);
            const unsigned b2 = __ballot_sync(0xffffffffu, v[k].z != 0.f);
            const unsigned b3 = __ballot_sync(0xffffffffu, v[k].w != 0.f);
            if (lane == 0) {
                const int wi = (k * 8 + w) << 2;
                mask[wi + 0] = b0; mask[wi + 1] = b1;
                mask[wi + 2] = b2; mask[wi + 3] = b3;
            }
        }
        __syncthreads();

        // ---- deterministic compaction ----
        const unsigned myword = mask[tid];
        const int c = __popc(myword);
        int incl = c;
#pragma unroll
        for (int o = 1; o < 32; o <<= 1) {
            const int x = __shfl_up_sync(0xffffffffu, incl, o);
            if (lane >= o) incl += x;
        }
        if (lane == 31) wsum[w] = incl;
        __syncthreads();
        if (tid == 0) {
            int run = 0;
            for (int q = 0; q < 8; q++) { wbase[q] = run; run += wsum[q]; }
            cnt_s = run < MAXNZ ? run : MAXNZ;
        }
        __syncthreads();
        {
            const int basej = ((tid >> 5) << 10) + (((tid >> 2) & 7) << 7) + (tid & 3);
            int off = wbase[w] + incl - c;
            unsigned m = myword;
            while (m) {
                const int b = __ffs(m) - 1;
                m &= m - 1;
                if (off < MAXNZ) jlist[off] = (unsigned short)(basej + (b << 2));
                off++;
            }
        }
        __syncthreads();
        const int cnt = cnt_s;

        const float srci = __ldg(&g_src[i]);
        float px = srci + dmax;
        px = fmaxf(px, ALPHA * px);
        const float px14 = px * LOG2E;

        // ---- gather with inline proxy-softmax (fp16 Whh, fp32 acc) ----
        const int g = lane >> 3;
        const int s8 = lane & 7;
        const uint4* whh4 = reinterpret_cast<const uint4*>(g_Whh);
        float acc[8] = {};
        float den = 0.f;

        for (int base = (w << 2); base < cnt; base += 64) {
            const int idx0 = base + g;
            const int idx1 = base + 32 + g;
            int j0 = 0, j1 = 0;
            bool ok0 = idx0 < cnt, ok1 = idx1 < cnt;
            if (ok0) j0 = jlist[idx0];
            if (ok1) j1 = jlist[idx1];
            const float d0 = __ldg(&g_dst[j0]);
            const float d1 = __ldg(&g_dst[j1]);
            const uint4 v0 = __ldg(&whh4[j0 * 8 + s8]);
            const uint4 v1 = __ldg(&whh4[j1 * 8 + s8]);
            float e0 = srci + d0, e1 = srci + d1;
            e0 = fmaxf(e0, ALPHA * e0);
            e1 = fmaxf(e1, ALPHA * e1);
            float p0 = ok0 ? ex2f(fmaf(e0, LOG2E, -px14)) : 0.f;
            float p1 = ok1 ? ex2f(fmaf(e1, LOG2E, -px14)) : 0.f;
            den += p0 + p1;
            const __half2* h0 = reinterpret_cast<const __half2*>(&v0);
            const __half2* h1 = reinterpret_cast<const __half2*>(&v1);
#pragma unroll
            for (int q = 0; q < 4; q++) {
                const float2 f0 = __half22float2(h0[q]);
                const float2 f1 = __half22float2(h1[q]);
                acc[2 * q]     += p0 * f0.x + p1 * f1.x;
                acc[2 * q + 1] += p0 * f0.y + p1 * f1.y;
            }
        }

        // den: 32-lane sum = 8x true sum -> /8 at the end
#pragma unroll
        for (int o = 16; o; o >>= 1) den += __shfl_xor_sync(0xffffffffu, den, o);
        if (lane == 0) fred[w] = den;

        const int part = (w << 2) + g;
#pragma unroll
        for (int q = 0; q < 8; q++) acc_red[part][s8 * 8 + q] = acc[q];
        __syncthreads();
        if (tid == 0) {
            float s = 0.f;
            for (int q = 0; q < 8; q++) s += fred[q];
            den_s = s * 0.125f;
        }

        // tree reduce 32 partials -> 4 -> 1 (deterministic)
        const int f = tid & 63;
        const int c4 = tid >> 6;
        float sp = 0.f;
#pragma unroll
        for (int q = 0; q < 8; q++) sp += acc_red[c4 * 8 + q][f];
        fin[c4][f] = sp;
        __syncthreads();

        if (tid < OUT_F) {
            float vv = (fin[0][tid] + fin[1][tid] + fin[2][tid] + fin[3][tid]) / den_s;
            vv = vv > 0.f ? vv : expm1f(vv);  // ELU
            out[(size_t)i * OUT_F + tid] = vv;
        }
        __syncthreads();          // fin/acc_red/fred reusable next row
    }
}

// ---------------------------------------------------------------------------
// inputs: h [8192,256] f32, adj [8192,8192] f32, W [256,64] f32, a [128,1] f32
// output: [8192,64] f32
// ---------------------------------------------------------------------------
extern "C" void kernel_launch(void* const* d_in, const int* in_sizes, int n_in,
                              void* d_out, int out_size) {
    const float* h   = (const float*)d_in[0];
    const float* adj = (const float*)d_in[1];
    const float* W   = (const float*)d_in[2];
    const float* a   = (const float*)d_in[3];
    float* out = (float*)d_out;

    wh_kernel<<<NWHBLK, 128>>>(h, W, a);
    attn_kernel<<<N_NODES / ROWS_PB, 256>>>(adj, out);
}

// round 10
// speedup vs baseline: 1.0936x; 1.0936x over previous
#include <cuda_runtime.h>
#include <cuda_fp16.h>
#include <cstdint>

#define N_NODES 8192
#define IN_F 256
#define OUT_F 64
#define ALPHA 0.3f
#define LOG2E 1.4426950408889634f
#define MAXNZ 1024
#define NWHBLK 256   // 32 rows per block

// ---------------- device scratch (no allocations allowed) ----------------
__device__ __half g_Whh[N_NODES * OUT_F];   // Wh fp16 [8192][64], 1 MB (L2-resident)
__device__ float g_src2[N_NODES];           // src * log2e
__device__ float g_dst2[N_NODES];           // dst * log2e
__device__ float g_blockmax[NWHBLK];        // per-block max of dst*log2e

__device__ __forceinline__ float ex2f(float x) {
    float r;
    asm("ex2.approx.f32 %0, %1;" : "=f"(r) : "f"(x));
    return r;
}

// ---------------------------------------------------------------------------
// Kernel 1: Wh = h @ W (fp16 out), scaled src/dst projections, per-block max.
// Block = 32 rows, 256 threads (thread = 2 rows x 4 feats). h tile staged once
// (32 KB, one sync); W read via __ldg (64 KB, L1-resident, coalesced float4).
// Mainloop is barrier-free and FFMA-pipe bound.
// ---------------------------------------------------------------------------
__global__ __launch_bounds__(256) void wh_kernel(const float* __restrict__ h,
                                                 const float* __restrict__ W,
                                                 const float* __restrict__ a) {
    __shared__ float sh[32][260];   // h tile [row][k], padded (stride 260)
    __shared__ float dtile[32];
    const int tid = threadIdx.x;
    const int tx = tid & 15;        // feat group (4 feats)
    const int ty = tid >> 4;        // row pair (rows 2ty, 2ty+1)
    const int I0 = blockIdx.x * 32;

    // ---- stage h tile: 2048 float4 slots, 8 per thread ----
#pragma unroll
    for (int it = 0; it < 8; it++) {
        const int idx = tid + it * 256;
        const int r = idx >> 6, c4 = idx & 63;
        *reinterpret_cast<float4*>(&sh[r][c4 * 4]) =
            __ldg(reinterpret_cast<const float4*>(&h[(size_t)(I0 + r) * IN_F]) + c4);
    }
    __syncthreads();

    const float4* W4 = reinterpret_cast<const float4*>(W);
    float acc0[4] = {}, acc1[4] = {};

    // ---- barrier-free mainloop: k unrolled x4 ----
#pragma unroll 4
    for (int k = 0; k < IN_F; k += 4) {
        const float4 ha = *reinterpret_cast<const float4*>(&sh[ty * 2][k]);
        const float4 hb = *reinterpret_cast<const float4*>(&sh[ty * 2 + 1][k]);
        const float4 w0 = __ldg(&W4[(k + 0) * 16 + tx]);
        const float4 w1 = __ldg(&W4[(k + 1) * 16 + tx]);
        const float4 w2 = __ldg(&W4[(k + 2) * 16 + tx]);
        const float4 w3 = __ldg(&W4[(k + 3) * 16 + tx]);
        acc0[0] += ha.x * w0.x + ha.y * w1.x + ha.z * w2.x + ha.w * w3.x;
        acc0[1] += ha.x * w0.y + ha.y * w1.y + ha.z * w2.y + ha.w * w3.y;
        acc0[2] += ha.x * w0.z + ha.y * w1.z + ha.z * w2.z + ha.w * w3.z;
        acc0[3] += ha.x * w0.w + ha.y * w1.w + ha.z * w2.w + ha.w * w3.w;
        acc1[0] += hb.x * w0.x + hb.y * w1.x + hb.z * w2.x + hb.w * w3.x;
        acc1[1] += hb.x * w0.y + hb.y * w1.y + hb.z * w2.y + hb.w * w3.y;
        acc1[2] += hb.x * w0.z + hb.y * w1.z + hb.z * w2.z + hb.w * w3.z;
        acc1[3] += hb.x * w0.w + hb.y * w1.w + hb.z * w2.w + hb.w * w3.w;
    }

    // ---- fp16 Wh stores (8 B per row per thread, coalesced across tx) ----
    {
        const __half2 r0a = __floats2half2_rn(acc0[0], acc0[1]);
        const __half2 r0b = __floats2half2_rn(acc0[2], acc0[3]);
        const __half2 r1a = __floats2half2_rn(acc1[0], acc1[1]);
        const __half2 r1b = __floats2half2_rn(acc1[2], acc1[3]);
        uint2 s0, s1;
        s0.x = *reinterpret_cast<const uint32_t*>(&r0a);
        s0.y = *reinterpret_cast<const uint32_t*>(&r0b);
        s1.x = *reinterpret_cast<const uint32_t*>(&r1a);
        s1.y = *reinterpret_cast<const uint32_t*>(&r1b);
        *reinterpret_cast<uint2*>(&g_Whh[(size_t)(I0 + ty * 2) * OUT_F + tx * 4]) = s0;
        *reinterpret_cast<uint2*>(&g_Whh[(size_t)(I0 + ty * 2 + 1) * OUT_F + tx * 4]) = s1;
    }

    // ---- src/dst projections (pre-scaled by LOG2E) ----
    const float4 as = *reinterpret_cast<const float4*>(&a[tx << 2]);
    const float4 ad = *reinterpret_cast<const float4*>(&a[OUT_F + (tx << 2)]);
    float sp0 = acc0[0] * as.x + acc0[1] * as.y + acc0[2] * as.z + acc0[3] * as.w;
    float dp0 = acc0[0] * ad.x + acc0[1] * ad.y + acc0[2] * ad.z + acc0[3] * ad.w;
    float sp1 = acc1[0] * as.x + acc1[1] * as.y + acc1[2] * as.z + acc1[3] * as.w;
    float dp1 = acc1[0] * ad.x + acc1[1] * ad.y + acc1[2] * ad.z + acc1[3] * ad.w;
#pragma unroll
    for (int o = 1; o < 16; o <<= 1) {   // reduce across the 16-lane tx group
        sp0 += __shfl_xor_sync(0xffffffffu, sp0, o);
        dp0 += __shfl_xor_sync(0xffffffffu, dp0, o);
        sp1 += __shfl_xor_sync(0xffffffffu, sp1, o);
        dp1 += __shfl_xor_sync(0xffffffffu, dp1, o);
    }
    if (tx == 0) {
        g_src2[I0 + ty * 2]     = sp0 * LOG2E;
        g_src2[I0 + ty * 2 + 1] = sp1 * LOG2E;
        g_dst2[I0 + ty * 2]     = dp0 * LOG2E;
        g_dst2[I0 + ty * 2 + 1] = dp1 * LOG2E;
        dtile[ty * 2]     = dp0 * LOG2E;
        dtile[ty * 2 + 1] = dp1 * LOG2E;
    }
    __syncthreads();
    if (tid == 0) {
        float mm = dtile[0];
        for (int q = 1; q < 32; q++) mm = fmaxf(mm, dtile[q]);
        g_blockmax[blockIdx.x] = mm;
    }
}

// ---------------------------------------------------------------------------
// Kernel 2: fused masked attention + aggregation + ELU. One block per row i.
// (Structure identical to the R8 winner; logits in log2 domain, one FMA less.)
//   A: 8 batched float4 adj loads (MLP=8) -> ballots -> 256-word bitmask
//   compaction: deterministic prefix-scan -> dense jlist
//   C: single-pass gather, p = ex2(lrelu2(src2+dst2) - px2), fp16 Whh, fp32 acc
// ---------------------------------------------------------------------------
__global__ __launch_bounds__(256) void attn_kernel(const float* __restrict__ adj,
                                                   float* __restrict__ out) {
    const int i = blockIdx.x;
    const int tid = threadIdx.x;
    const int w = tid >> 5;
    const int lane = tid & 31;

    __shared__ unsigned mask[256];
    __shared__ int wsum[8], wbase[8];
    __shared__ float fred[8];
    __shared__ int cnt_s;
    __shared__ float dmax_s, den_s;
    __shared__ unsigned short jlist[MAXNZ];
    __shared__ float acc_red[32][OUT_F];
    __shared__ float fin[4][OUT_F];

    const float4* adj4 = reinterpret_cast<const float4*>(adj + (size_t)i * N_NODES);

    // ---- Phase A: issue all 8 adj loads (MLP=8) ----
    float4 v[8];
#pragma unroll
    for (int k = 0; k < 8; k++) v[k] = __ldg(&adj4[k * 256 + tid]);

    // ---- dmax reduction (overlaps adj load latency) ----
    {
        float m = g_blockmax[tid];
#pragma unroll
        for (int o = 16; o; o >>= 1) m = fmaxf(m, __shfl_xor_sync(0xffffffffu, m, o));
        if (lane == 0) fred[w] = m;
    }
    const float srci = __ldg(&g_src2[i]);

    // ---- ballots -> bitmask ----
#pragma unroll
    for (int k = 0; k < 8; k++) {
        const unsigned b0 = __ballot_sync(0xffffffffu, v[k].x != 0.f);
        const unsigned b1 = __ballot_sync(0xffffffffu, v[k].y != 0.f);
        const unsigned b2 = __ballot_sync(0xffffffffu, v[k].z != 0.f);
        const unsigned b3 = __ballot_sync(0xffffffffu, v[k].w != 0.f);
        if (lane == 0) {
            const int wi = (k * 8 + w) << 2;
            mask[wi + 0] = b0; mask[wi + 1] = b1;
            mask[wi + 2] = b2; mask[wi + 3] = b3;
        }
    }
    __syncthreads();
    if (tid == 0) {
        float mm = fred[0];
        for (int q = 1; q < 8; q++) mm = fmaxf(mm, fred[q]);
        dmax_s = mm;
    }

    // ---- deterministic compaction: exclusive scan of per-word popcounts ----
    const unsigned myword = mask[tid];
    const int c = __popc(myword);
    int incl = c;
#pragma unroll
    for (int o = 1; o < 32; o <<= 1) {
        const int x = __shfl_up_sync(0xffffffffu, incl, o);
        if (lane >= o) incl += x;
    }
    if (lane == 31) wsum[w] = incl;
    __syncthreads();
    if (tid == 0) {
        int run = 0;
        for (int q = 0; q < 8; q++) { wbase[q] = run; run += wsum[q]; }
        cnt_s = run < MAXNZ ? run : MAXNZ;
    }
    __syncthreads();
    {
        // word tid: k = tid>>5, w' = (tid>>2)&7, comp = tid&3
        const int basej = ((tid >> 5) << 10) + (((tid >> 2) & 7) << 7) + (tid & 3);
        int off = wbase[w] + incl - c;
        unsigned m = myword;
        while (m) {
            const int b = __ffs(m) - 1;
            m &= m - 1;
            if (off < MAXNZ) jlist[off] = (unsigned short)(basej + (b << 2));
            off++;
        }
    }
    __syncthreads();
    const int cnt = cnt_s;

    // proxy upper bound in log2 domain: px2 >= lrelu2(src2 + dst2_j) for all j
    float px2 = srci + dmax_s;
    px2 = fmaxf(px2, ALPHA * px2);

    // ---- Phase C: gather with inline p (fp16 Whh rows, fp32 acc, unroll x2) ----
    const int g = lane >> 3;   // 4 nz-groups per warp
    const int s8 = lane & 7;   // 8 lanes x 8 halves = 64 features
    const uint4* whh4 = reinterpret_cast<const uint4*>(g_Whh);
    float acc[8] = {};
    float den = 0.f;

    for (int base = (w << 2); base < cnt; base += 64) {
        const int idx0 = base + g;
        const int idx1 = base + 32 + g;
        int j0 = 0, j1 = 0;
        bool ok0 = idx0 < cnt, ok1 = idx1 < cnt;
        if (ok0) j0 = jlist[idx0];
        if (ok1) j1 = jlist[idx1];
        const float d0 = __ldg(&g_dst2[j0]);
        const float d1 = __ldg(&g_dst2[j1]);
        const uint4 v0 = __ldg(&whh4[j0 * 8 + s8]);
        const uint4 v1 = __ldg(&whh4[j1 * 8 + s8]);
        float e0 = srci + d0, e1 = srci + d1;
        e0 = fmaxf(e0, ALPHA * e0);
        e1 = fmaxf(e1, ALPHA * e1);
        float p0 = ok0 ? ex2f(e0 - px2) : 0.f;
        float p1 = ok1 ? ex2f(e1 - px2) : 0.f;
        den += p0 + p1;
        const __half2* h0 = reinterpret_cast<const __half2*>(&v0);
        const __half2* h1 = reinterpret_cast<const __half2*>(&v1);
#pragma unroll
        for (int q = 0; q < 4; q++) {
            const float2 f0 = __half22float2(h0[q]);
            const float2 f1 = __half22float2(h1[q]);
            acc[2 * q]     += p0 * f0.x + p1 * f1.x;
            acc[2 * q + 1] += p0 * f0.y + p1 * f1.y;
        }
    }

    // den: all 32 lanes summed = 8x true sum (8 lanes per group) -> /8 later
#pragma unroll
    for (int o = 16; o; o >>= 1) den += __shfl_xor_sync(0xffffffffu, den, o);
    if (lane == 0) fred[w] = den;

    const int part = (w << 2) + g;  // 0..31
#pragma unroll
    for (int q = 0; q < 8; q++) acc_red[part][s8 * 8 + q] = acc[q];
    __syncthreads();
    if (tid == 0) {
        float s = 0.f;
        for (int q = 0; q < 8; q++) s += fred[q];
        den_s = s * 0.125f;
    }

    // tree reduce 32 partials -> 4 -> 1, fixed order (deterministic)
    const int f = tid & 63;
    const int c4 = tid >> 6;  // 0..3
    float sp = 0.f;
#pragma unroll
    for (int q = 0; q < 8; q++) sp += acc_red[c4 * 8 + q][f];
    fin[c4][f] = sp;
    __syncthreads();

    if (tid < OUT_F) {
        float vv = (fin[0][tid] + fin[1][tid] + fin[2][tid] + fin[3][tid]) / den_s;
        vv = vv > 0.f ? vv : expm1f(vv);  // ELU
        out[(size_t)i * OUT_F + tid] = vv;
    }
}

// ---------------------------------------------------------------------------
// inputs: h [8192,256] f32, adj [8192,8192] f32, W [256,64] f32, a [128,1] f32
// output: [8192,64] f32
// ---------------------------------------------------------------------------
extern "C" void kernel_launch(void* const* d_in, const int* in_sizes, int n_in,
                              void* d_out, int out_size) {
    const float* h   = (const float*)d_in[0];
    const float* adj = (const float*)d_in[1];
    const float* W   = (const float*)d_in[2];
    const float* a   = (const float*)d_in[3];
    float* out = (float*)d_out;

    wh_kernel<<<NWHBLK, 256>>>(h, W, a);
    attn_kernel<<<N_NODES, 256>>>(adj, out);
}